// round 8
// baseline (speedup 1.0000x reference)
#include <cuda_runtime.h>
#include <stdint.h>

// Strategy: hash the ~100k QUERY keys into (a) an exact open-addressing table
// (4MB, L2-resident) and (b) a 2^20-bit Bloom filter (128KB). The 10M data
// triples then stream through, testing the Bloom in SHARED MEMORY (copied per
// CTA); only ~3% false positives + true hits touch the exact table in L2.
//
// Inputs are int32 (JAX x64 disabled). Triple key (h*15000+r)*15000+t wraps
// in int32 arithmetic; replicated exactly with uint32 math.
#define QT_LOG2 19
#define QT_SIZE (1u << QT_LOG2)
#define QT_MASK (QT_SIZE - 1u)
#define EMPTY64 0xFFFFFFFFFFFFFFFFull
#define FOUND_BIT (1ull << 32)
#define N_ENT 15000u

#define BLOOM_LOG2 20
#define BLOOM_BITS (1u << BLOOM_LOG2)
#define BLOOM_MASK (BLOOM_BITS - 1u)
#define BLOOM_WORDS (BLOOM_BITS / 32)        // 32768 words = 128KB

#define MAX_Q (1 << 17)                       // up to 131072 queries

__device__ unsigned long long g_qtable[QT_SIZE];   // 4MB
__device__ uint32_t g_bloom[BLOOM_WORDS];          // 128KB
__device__ int g_qslot[MAX_Q];                     // slot per query

__device__ __forceinline__ uint32_t make_key(uint32_t h, uint32_t r, uint32_t t) {
    return (h * N_ENT + r) * N_ENT + t;   // wraps mod 2^32 == int32 reference
}

__device__ __forceinline__ unsigned long long mix64(uint32_t k) {
    unsigned long long x = k;
    x ^= x >> 30; x *= 0xbf58476d1ce4e5b9ull;
    x ^= x >> 27; x *= 0x94d049bb133111ebull;
    x ^= x >> 31;
    return x;
}

__device__ __forceinline__ unsigned long long ld_cg64(const unsigned long long* p) {
    unsigned long long v;
    asm volatile("ld.global.cg.u64 %0, [%1];" : "=l"(v) : "l"(p));
    return v;
}
__device__ __forceinline__ void st_cg64(unsigned long long* p, unsigned long long v) {
    asm volatile("st.global.cg.u64 [%0], %1;" :: "l"(p), "l"(v));
}

// ---- Pass A: clear qtable + bloom ----
__global__ void clear_kernel() {
    uint32_t tid = blockIdx.x * blockDim.x + threadIdx.x;
    uint32_t stride = gridDim.x * blockDim.x;
    ulonglong2* p = reinterpret_cast<ulonglong2*>(g_qtable);
    ulonglong2 v; v.x = EMPTY64; v.y = EMPTY64;
    for (uint32_t i = tid; i < QT_SIZE / 2; i += stride) p[i] = v;
    for (uint32_t i = tid; i < BLOOM_WORDS; i += stride) g_bloom[i] = 0u;
}

// ---- Pass B: insert query keys, set bloom bits, record slots ----
__global__ void insert_queries_kernel(const int* __restrict__ heads,
                                      const int* __restrict__ rels,
                                      const int* __restrict__ tails, int q) {
    int i = blockIdx.x * blockDim.x + threadIdx.x;
    if (i >= q) return;
    uint32_t key = make_key((uint32_t)heads[i], (uint32_t)rels[i], (uint32_t)tails[i]);
    unsigned long long h64 = mix64(key);
    uint32_t b1 = (uint32_t)h64 & BLOOM_MASK;
    uint32_t b2 = (uint32_t)(h64 >> 20) & BLOOM_MASK;
    atomicOr(&g_bloom[b1 >> 5], 1u << (b1 & 31));
    atomicOr(&g_bloom[b2 >> 5], 1u << (b2 & 31));

    uint32_t slot = (uint32_t)(h64 >> 40) & QT_MASK;
    while (true) {
        unsigned long long v = ld_cg64(&g_qtable[slot]);
        if (v != EMPTY64 && (uint32_t)v == key) break;      // dup already in
        if (v == EMPTY64) {
            unsigned long long prev =
                atomicCAS(&g_qtable[slot], EMPTY64, (unsigned long long)key);
            if (prev == EMPTY64 || (uint32_t)prev == key) break;
        }
        slot = (slot + 1) & QT_MASK;
    }
    g_qslot[i] = (int)slot;
}

// ---- Pass C: stream data through smem bloom; mark exact table on hits ----
__device__ __forceinline__ void mark_one(const uint32_t* s_bloom,
                                         uint32_t h, uint32_t r, uint32_t t) {
    uint32_t key = make_key(h, r, t);
    unsigned long long h64 = mix64(key);
    uint32_t b1 = (uint32_t)h64 & BLOOM_MASK;
    if (!((s_bloom[b1 >> 5] >> (b1 & 31)) & 1u)) return;
    uint32_t b2 = (uint32_t)(h64 >> 20) & BLOOM_MASK;
    if (!((s_bloom[b2 >> 5] >> (b2 & 31)) & 1u)) return;
    uint32_t slot = (uint32_t)(h64 >> 40) & QT_MASK;
    while (true) {
        unsigned long long v = ld_cg64(&g_qtable[slot]);
        if (v == EMPTY64) break;                             // bloom false pos
        if ((uint32_t)v == key) {
            if (!(v & FOUND_BIT))
                st_cg64(&g_qtable[slot], (unsigned long long)key | FOUND_BIT);
            break;
        }
        slot = (slot + 1) & QT_MASK;
    }
}

__global__ void mark_kernel(const int* __restrict__ data, int n) {
    extern __shared__ uint32_t s_bloom[];
    for (uint32_t i = threadIdx.x; i < BLOOM_WORDS; i += blockDim.x)
        s_bloom[i] = g_bloom[i];
    __syncthreads();

    uint32_t gtid = blockIdx.x * blockDim.x + threadIdx.x;
    uint32_t gstride = gridDim.x * blockDim.x;

    if ((n & 3) == 0) {
        int n4 = n >> 2;
        const int4* d0 = reinterpret_cast<const int4*>(data);
        const int4* d1 = reinterpret_cast<const int4*>(data + n);
        const int4* d2 = reinterpret_cast<const int4*>(data + 2 * n);
        for (uint32_t i = gtid; i < (uint32_t)n4; i += gstride) {
            int4 h = d0[i], r = d1[i], t = d2[i];
            mark_one(s_bloom, (uint32_t)h.x, (uint32_t)r.x, (uint32_t)t.x);
            mark_one(s_bloom, (uint32_t)h.y, (uint32_t)r.y, (uint32_t)t.y);
            mark_one(s_bloom, (uint32_t)h.z, (uint32_t)r.z, (uint32_t)t.z);
            mark_one(s_bloom, (uint32_t)h.w, (uint32_t)r.w, (uint32_t)t.w);
        }
    } else {
        for (uint32_t i = gtid; i < (uint32_t)n; i += gstride)
            mark_one(s_bloom, (uint32_t)data[i], (uint32_t)data[n + i],
                     (uint32_t)data[2 * n + i]);
    }
}

// ---- Pass D: resolve via recorded slot ----
__global__ void resolve_kernel(float* __restrict__ out, int q) {
    int i = blockIdx.x * blockDim.x + threadIdx.x;
    if (i >= q) return;
    unsigned long long v = ld_cg64(&g_qtable[g_qslot[i]]);
    out[i] = (v & FOUND_BIT) ? 5.0f : -5.0f;
}

extern "C" void kernel_launch(void* const* d_in, const int* in_sizes, int n_in,
                              void* d_out, int out_size) {
    const int* heads = (const int*)d_in[0];
    const int* rels  = (const int*)d_in[1];
    const int* tails = (const int*)d_in[2];
    const int* data  = (const int*)d_in[3];
    float* out = (float*)d_out;

    const int q = in_sizes[0];
    const int n = in_sizes[3] / 3;
    const int threads = 256;

    // opt-in to 128KB dynamic smem for mark_kernel (idempotent, no alloc)
    cudaFuncSetAttribute(mark_kernel,
                         cudaFuncAttributeMaxDynamicSharedMemorySize,
                         BLOOM_WORDS * 4);

    // A: clear 4MB qtable + 128KB bloom
    clear_kernel<<<148 * 4, threads>>>();
    // B: insert query keys (bloom + exact table + slot record)
    insert_queries_kernel<<<(q + threads - 1) / threads, threads>>>(heads, rels, tails, q);
    // C: stream data; smem-bloom prefilter, exact-table mark
    mark_kernel<<<148, 1024, BLOOM_WORDS * 4>>>(data, n);
    // D: write +/-5 per query from recorded slot
    resolve_kernel<<<(q + threads - 1) / threads, threads>>>(out, q);
}

// round 9
// speedup vs baseline: 1.0529x; 1.0529x over previous
#include <cuda_runtime.h>
#include <stdint.h>

// Strategy (R6 skeleton + low-risk smem prefilter):
//  - hash ~100k QUERY keys into exact table (2MB, L2) + 2^18-bit bloom (32KB)
//  - stream 10M data triples; test k=1 bloom bit in STATIC smem (one LDS,
//    32-bit hash only); only ~32% proceed to the random L2 probe
//  - resolve reads each query's recorded slot
//
// Inputs are int32 (JAX x64 disabled). Triple key (h*15000+r)*15000+t wraps
// in int32 arithmetic; replicated exactly with uint32 math.
#define QT_LOG2 18
#define QT_SIZE (1u << QT_LOG2)
#define QT_MASK (QT_SIZE - 1u)
#define EMPTY64 0xFFFFFFFFFFFFFFFFull
#define FOUND_BIT (1ull << 32)
#define N_ENT 15000u

#define BLOOM_LOG2 18
#define BLOOM_BITS (1u << BLOOM_LOG2)
#define BLOOM_MASK (BLOOM_BITS - 1u)
#define BLOOM_WORDS (BLOOM_BITS / 32)    // 8192 words = 32KB (static smem OK)

#define MAX_Q (1 << 17)

__device__ unsigned long long g_qtable[QT_SIZE];   // 2MB
__device__ uint32_t g_bloom[BLOOM_WORDS];          // 32KB
__device__ int g_qslot[MAX_Q];

__device__ __forceinline__ uint32_t make_key(uint32_t h, uint32_t r, uint32_t t) {
    return (h * N_ENT + r) * N_ENT + t;   // wraps mod 2^32 == int32 reference
}

__device__ __forceinline__ uint32_t fmix32(uint32_t x) {
    x ^= x >> 16; x *= 0x85ebca6bu;
    x ^= x >> 13; x *= 0xc2b2ae35u;
    x ^= x >> 16;
    return x;
}

__device__ __forceinline__ unsigned long long ld_cg64(const unsigned long long* p) {
    unsigned long long v;
    asm volatile("ld.global.cg.u64 %0, [%1];" : "=l"(v) : "l"(p));
    return v;
}
__device__ __forceinline__ void st_cg64(unsigned long long* p, unsigned long long v) {
    asm volatile("st.global.cg.u64 [%0], %1;" :: "l"(p), "l"(v));
}

// ---- Pass A: clear qtable + bloom ----
__global__ void clear_kernel() {
    uint32_t tid = blockIdx.x * blockDim.x + threadIdx.x;
    uint32_t stride = gridDim.x * blockDim.x;
    ulonglong2* p = reinterpret_cast<ulonglong2*>(g_qtable);
    ulonglong2 v; v.x = EMPTY64; v.y = EMPTY64;
    for (uint32_t i = tid; i < QT_SIZE / 2; i += stride) p[i] = v;
    for (uint32_t i = tid; i < BLOOM_WORDS; i += stride) g_bloom[i] = 0u;
}

// ---- Pass B: insert query keys, set bloom bit, record slot ----
__global__ void insert_queries_kernel(const int* __restrict__ heads,
                                      const int* __restrict__ rels,
                                      const int* __restrict__ tails, int q) {
    int i = blockIdx.x * blockDim.x + threadIdx.x;
    if (i >= q) return;
    uint32_t key = make_key((uint32_t)heads[i], (uint32_t)rels[i], (uint32_t)tails[i]);
    uint32_t hh = fmix32(key);
    uint32_t b = hh & BLOOM_MASK;
    atomicOr(&g_bloom[b >> 5], 1u << (b & 31));

    uint32_t slot = (hh >> 13) & QT_MASK;
    while (true) {
        unsigned long long v = ld_cg64(&g_qtable[slot]);
        if (v != EMPTY64 && (uint32_t)v == key) break;      // dup
        if (v == EMPTY64) {
            unsigned long long prev =
                atomicCAS(&g_qtable[slot], EMPTY64, (unsigned long long)key);
            if (prev == EMPTY64 || (uint32_t)prev == key) break;
        }
        slot = (slot + 1) & QT_MASK;
    }
    g_qslot[i] = (int)slot;
}

// ---- Pass C: stream data; smem k=1 bloom prefilter, then exact probe ----
__device__ __forceinline__ void probe_mark(uint32_t key, uint32_t hh) {
    uint32_t slot = (hh >> 13) & QT_MASK;
    while (true) {
        unsigned long long v = ld_cg64(&g_qtable[slot]);
        if (v == EMPTY64) break;                           // false positive
        if ((uint32_t)v == key) {
            if (!(v & FOUND_BIT))
                st_cg64(&g_qtable[slot], (unsigned long long)key | FOUND_BIT);
            break;
        }
        slot = (slot + 1) & QT_MASK;
    }
}

__global__ void __launch_bounds__(512, 2) mark_kernel(const int* __restrict__ data, int n) {
    __shared__ uint32_t s_bloom[BLOOM_WORDS];   // 32KB static
    for (uint32_t i = threadIdx.x; i < BLOOM_WORDS; i += blockDim.x)
        s_bloom[i] = g_bloom[i];
    __syncthreads();

    uint32_t gtid = blockIdx.x * blockDim.x + threadIdx.x;
    uint32_t gstride = gridDim.x * blockDim.x;

    if ((n & 3) == 0) {
        int n4 = n >> 2;
        const int4* d0 = reinterpret_cast<const int4*>(data);
        const int4* d1 = reinterpret_cast<const int4*>(data + n);
        const int4* d2 = reinterpret_cast<const int4*>(data + 2 * n);
        for (uint32_t i = gtid; i < (uint32_t)n4; i += gstride) {
            int4 h = d0[i], r = d1[i], t = d2[i];
            uint32_t k0 = make_key((uint32_t)h.x, (uint32_t)r.x, (uint32_t)t.x);
            uint32_t k1 = make_key((uint32_t)h.y, (uint32_t)r.y, (uint32_t)t.y);
            uint32_t k2 = make_key((uint32_t)h.z, (uint32_t)r.z, (uint32_t)t.z);
            uint32_t k3 = make_key((uint32_t)h.w, (uint32_t)r.w, (uint32_t)t.w);
            uint32_t h0 = fmix32(k0), h1 = fmix32(k1),
                     h2 = fmix32(k2), h3 = fmix32(k3);
            // branchless bloom tests: 4 independent LDS in flight
            uint32_t b0 = h0 & BLOOM_MASK, b1 = h1 & BLOOM_MASK;
            uint32_t b2 = h2 & BLOOM_MASK, b3 = h3 & BLOOM_MASK;
            uint32_t w0 = s_bloom[b0 >> 5], w1 = s_bloom[b1 >> 5];
            uint32_t w2 = s_bloom[b2 >> 5], w3 = s_bloom[b3 >> 5];
            bool p0 = (w0 >> (b0 & 31)) & 1u;
            bool p1 = (w1 >> (b1 & 31)) & 1u;
            bool p2 = (w2 >> (b2 & 31)) & 1u;
            bool p3 = (w3 >> (b3 & 31)) & 1u;
            if (p0) probe_mark(k0, h0);
            if (p1) probe_mark(k1, h1);
            if (p2) probe_mark(k2, h2);
            if (p3) probe_mark(k3, h3);
        }
    } else {
        for (uint32_t i = gtid; i < (uint32_t)n; i += gstride) {
            uint32_t k = make_key((uint32_t)data[i], (uint32_t)data[n + i],
                                  (uint32_t)data[2 * n + i]);
            uint32_t hh = fmix32(k);
            uint32_t b = hh & BLOOM_MASK;
            if ((s_bloom[b >> 5] >> (b & 31)) & 1u) probe_mark(k, hh);
        }
    }
}

// ---- Pass D: resolve via recorded slot ----
__global__ void resolve_kernel(float* __restrict__ out, int q) {
    int i = blockIdx.x * blockDim.x + threadIdx.x;
    if (i >= q) return;
    unsigned long long v = ld_cg64(&g_qtable[g_qslot[i]]);
    out[i] = (v & FOUND_BIT) ? 5.0f : -5.0f;
}

extern "C" void kernel_launch(void* const* d_in, const int* in_sizes, int n_in,
                              void* d_out, int out_size) {
    const int* heads = (const int*)d_in[0];
    const int* rels  = (const int*)d_in[1];
    const int* tails = (const int*)d_in[2];
    const int* data  = (const int*)d_in[3];
    float* out = (float*)d_out;

    const int q = in_sizes[0];
    const int n = in_sizes[3] / 3;
    const int threads = 256;

    // A: clear 2MB qtable + 32KB bloom
    clear_kernel<<<148 * 4, threads>>>();
    // B: insert query keys
    insert_queries_kernel<<<(q + threads - 1) / threads, threads>>>(heads, rels, tails, q);
    // C: persistent CTAs, 2/SM: smem-bloom prefilter + exact-table mark
    mark_kernel<<<296, 512>>>(data, n);
    // D: write +/-5 per query from recorded slot
    resolve_kernel<<<(q + threads - 1) / threads, threads>>>(out, q);
}

// round 10
// speedup vs baseline: 2.1483x; 2.0403x over previous
#include <cuda_runtime.h>
#include <stdint.h>

// R6 skeleton (best: 86.5us), instruction-minimized hot path.
// Query keys -> exact open-addressing table (2MB, L2-resident); 10M data
// triples stream through with a 2-instr multiply-shift hash and a single
// expected probe load. Inputs are int32 (JAX x64 disabled); triple key
// (h*15000+r)*15000+t wraps in int32 == uint32 arithmetic.
#define QT_LOG2 19
#define QT_SIZE (1u << QT_LOG2)
#define QT_MASK (QT_SIZE - 1u)
#define EMPTY64 0xFFFFFFFFFFFFFFFFull
#define FOUND_BIT (1ull << 32)
#define N_ENT 15000u
#define MAX_Q (1 << 17)

__device__ unsigned long long g_qtable[QT_SIZE];   // 4MB? no: 2^19*8B = 4MB
__device__ int g_qslot[MAX_Q];

__device__ __forceinline__ uint32_t make_key(uint32_t h, uint32_t r, uint32_t t) {
    return (h * N_ENT + r) * N_ENT + t;   // wraps mod 2^32 == int32 reference
}

// Fibonacci multiply-shift: 1 IMAD + 1 SHF; top bits well-mixed.
__device__ __forceinline__ uint32_t hash_slot(uint32_t key) {
    return (key * 2654435769u) >> (32 - QT_LOG2);
}

__device__ __forceinline__ unsigned long long ld_cg64(const unsigned long long* p) {
    unsigned long long v;
    asm volatile("ld.global.cg.u64 %0, [%1];" : "=l"(v) : "l"(p));
    return v;
}
__device__ __forceinline__ void st_cg64(unsigned long long* p, unsigned long long v) {
    asm volatile("st.global.cg.u64 [%0], %1;" :: "l"(p), "l"(v));
}

// ---- Pass A: clear table ----
__global__ void clear_kernel() {
    uint32_t tid = blockIdx.x * blockDim.x + threadIdx.x;
    uint32_t stride = gridDim.x * blockDim.x;
    ulonglong2* p = reinterpret_cast<ulonglong2*>(g_qtable);
    ulonglong2 v; v.x = EMPTY64; v.y = EMPTY64;
    for (uint32_t i = tid; i < QT_SIZE / 2; i += stride) p[i] = v;
}

// ---- Pass B: insert query keys, record slot ----
__global__ void insert_queries_kernel(const int* __restrict__ heads,
                                      const int* __restrict__ rels,
                                      const int* __restrict__ tails, int q) {
    int i = blockIdx.x * blockDim.x + threadIdx.x;
    if (i >= q) return;
    uint32_t key = make_key((uint32_t)heads[i], (uint32_t)rels[i], (uint32_t)tails[i]);
    uint32_t slot = hash_slot(key);
    while (true) {
        unsigned long long v = ld_cg64(&g_qtable[slot]);
        if (v != EMPTY64 && (uint32_t)v == key) break;      // dup
        if (v == EMPTY64) {
            unsigned long long prev =
                atomicCAS(&g_qtable[slot], EMPTY64, (unsigned long long)key);
            if (prev == EMPTY64 || (uint32_t)prev == key) break;
        }
        slot = (slot + 1) & QT_MASK;
    }
    g_qslot[i] = (int)slot;
}

// ---- Pass C: stream data, minimal-instruction probe ----
__device__ __forceinline__ void probe_mark(uint32_t key) {
    uint32_t slot = hash_slot(key);
    unsigned long long v = ld_cg64(&g_qtable[slot]);
    if (v == EMPTY64) return;                 // expected path: 1 load, done
    while (true) {
        if ((uint32_t)v == key) {
            if (!(v & FOUND_BIT))
                st_cg64(&g_qtable[slot], (unsigned long long)key | FOUND_BIT);
            return;
        }
        slot = (slot + 1) & QT_MASK;
        v = ld_cg64(&g_qtable[slot]);
        if (v == EMPTY64) return;
    }
}

__global__ void mark_kernel(const int* __restrict__ data, int n4, int n) {
    int i = blockIdx.x * blockDim.x + threadIdx.x;
    if (i < n4) {
        const int4* d0 = reinterpret_cast<const int4*>(data);
        const int4* d1 = reinterpret_cast<const int4*>(data + n);
        const int4* d2 = reinterpret_cast<const int4*>(data + 2 * n);
        int4 h = d0[i], r = d1[i], t = d2[i];
        uint32_t k0 = make_key((uint32_t)h.x, (uint32_t)r.x, (uint32_t)t.x);
        uint32_t k1 = make_key((uint32_t)h.y, (uint32_t)r.y, (uint32_t)t.y);
        uint32_t k2 = make_key((uint32_t)h.z, (uint32_t)r.z, (uint32_t)t.z);
        uint32_t k3 = make_key((uint32_t)h.w, (uint32_t)r.w, (uint32_t)t.w);
        probe_mark(k0);
        probe_mark(k1);
        probe_mark(k2);
        probe_mark(k3);
    }
    // tail elements (n not divisible by 4)
    int tail_start = n4 * 4;
    int ti = tail_start + i;
    if (i < n - tail_start) {
        uint32_t k = make_key((uint32_t)data[ti], (uint32_t)data[n + ti],
                              (uint32_t)data[2 * n + ti]);
        probe_mark(k);
    }
}

// ---- Pass D: resolve via recorded slot ----
__global__ void resolve_kernel(float* __restrict__ out, int q) {
    int i = blockIdx.x * blockDim.x + threadIdx.x;
    if (i >= q) return;
    unsigned long long v = ld_cg64(&g_qtable[g_qslot[i]]);
    out[i] = (v & FOUND_BIT) ? 5.0f : -5.0f;
}

extern "C" void kernel_launch(void* const* d_in, const int* in_sizes, int n_in,
                              void* d_out, int out_size) {
    const int* heads = (const int*)d_in[0];
    const int* rels  = (const int*)d_in[1];
    const int* tails = (const int*)d_in[2];
    const int* data  = (const int*)d_in[3];
    float* out = (float*)d_out;

    const int q = in_sizes[0];
    const int n = in_sizes[3] / 3;
    const int n4 = n >> 2;
    const int threads = 256;

    // A: clear 4MB qtable
    clear_kernel<<<148 * 4, threads>>>();
    // B: insert query keys + record slots
    insert_queries_kernel<<<(q + threads - 1) / threads, threads>>>(heads, rels, tails, q);
    // C: one thread per 4 keys, direct minimal probe
    mark_kernel<<<(n4 + threads - 1) / threads, threads>>>(data, n4, n);
    // D: write +/-5 per query from recorded slot
    resolve_kernel<<<(q + threads - 1) / threads, threads>>>(out, q);
}